// round 14
// baseline (speedup 1.0000x reference)
#include <cuda_runtime.h>
#include <cuda_bf16.h>
#include <math.h>
#include <stdint.h>

#define DM    1024
#define NIMU  72
#define NOUT  864
#define NPAD  896
#define KC    64
#define NCH   (DM / KC)
#define TILEB 16384
#define STAGEB (4 * TILEB)
#define WSPLIT_BLOCKS ((DM / 32) * (NPAD / 32))   // 896

__device__ __nv_bfloat16 g_xn_hi[4096 * DM];
__device__ __nv_bfloat16 g_xn_lo[4096 * DM];
__device__ __nv_bfloat16 g_wT_hi[NPAD * DM];
__device__ __nv_bfloat16 g_wT_lo[NPAD * DM];
__device__ float         g_p[4096 * NPAD];
__device__ float         g_osc[4096 * NIMU * 8];

__device__ __forceinline__ uint32_t smem_u32(const void* p) {
    uint32_t a;
    asm("{ .reg .u64 t; cvta.to.shared.u64 t, %1; cvt.u32.u64 %0, t; }" : "=r"(a) : "l"(p));
    return a;
}
#define SWZ128(o) ((o) ^ (((o) >> 3) & 0x70))

__device__ __forceinline__ void cp16(uint32_t s, const void* g) {
    asm volatile("cp.async.cg.shared.global [%0], [%1], 16;"
                 :: "r"(s), "l"(__cvta_generic_to_global(g)) : "memory");
}
#define CP_COMMIT() asm volatile("cp.async.commit_group;" ::: "memory")
#define CP_WAIT(n)  asm volatile("cp.async.wait_group %0;" :: "n"(n) : "memory")

#define LDSM4(r0, r1, r2, r3, a) \
    asm volatile("ldmatrix.sync.aligned.m8n8.x4.shared.b16 {%0,%1,%2,%3}, [%4];" \
                 : "=r"(r0), "=r"(r1), "=r"(r2), "=r"(r3) : "r"(a))

#define MMA(d, a, b) \
    asm volatile("mma.sync.aligned.m16n8k16.row.col.f32.bf16.bf16.f32 " \
                 "{%0,%1,%2,%3}, {%4,%5,%6,%7}, {%8,%9}, {%0,%1,%2,%3};" \
                 : "+f"((d)[0]), "+f"((d)[1]), "+f"((d)[2]), "+f"((d)[3]) \
                 : "r"((a)[0]), "r"((a)[1]), "r"((a)[2]), "r"((a)[3]), \
                   "r"((b)[0]), "r"((b)[1]))

#define MULX2(d, a, b) asm("mul.rn.f32x2 %0, %1, %2;" : "=l"(d) : "l"(a), "l"(b))
#define FMAX2(d, a, b, c) asm("fma.rn.f32x2 %0, %1, %2, %3;" : "=l"(d) : "l"(a), "l"(b), "l"(c))
__device__ __forceinline__ unsigned long long packf2(float lo, float hi) {
    unsigned long long r;
    asm("mov.b64 %0, {%1, %2};" : "=l"(r) : "f"(lo), "f"(hi));
    return r;
}
__device__ __forceinline__ void unpackf2(float& lo, float& hi, unsigned long long v) {
    asm("mov.b64 {%0, %1}, %2;" : "=f"(lo), "=f"(hi) : "l"(v));
}

// ---- fused prep: LN-split [0,seq) | W-split [seq,seq+896) | zero-out [seq+896, ...) ----
__global__ __launch_bounds__(256) void prep_kernel(const float* __restrict__ x,
                                                   const float* __restrict__ gamma,
                                                   const float* __restrict__ beta,
                                                   const float* __restrict__ W,
                                                   float* __restrict__ out, int seq) {
    if ((int)blockIdx.x < seq) {
        int s = blockIdx.x, tid = threadIdx.x;
        const float4* xr = (const float4*)(x + (size_t)s * DM);
        float4 v = xr[tid];
        float sum = v.x + v.y + v.z + v.w;
        float sq  = v.x*v.x + v.y*v.y + v.z*v.z + v.w*v.w;
#pragma unroll
        for (int o = 16; o > 0; o >>= 1) {
            sum += __shfl_xor_sync(0xffffffffu, sum, o);
            sq  += __shfl_xor_sync(0xffffffffu, sq,  o);
        }
        __shared__ float ssum[8], ssq[8], s_mu, s_rs;
        int wid = tid >> 5, lane = tid & 31;
        if (lane == 0) { ssum[wid] = sum; ssq[wid] = sq; }
        __syncthreads();
        if (tid == 0) {
            float ts = 0.f, tq = 0.f;
#pragma unroll
            for (int i = 0; i < 8; i++) { ts += ssum[i]; tq += ssq[i]; }
            float mu  = ts * (1.0f / DM);
            float var = tq * (1.0f / DM) - mu * mu;
            s_mu = mu; s_rs = rsqrtf(var + 1e-5f);
        }
        __syncthreads();
        float mu = s_mu, rs = s_rs;
        size_t base = (size_t)s * DM + (size_t)tid * 4;
        float xv[4] = {v.x, v.y, v.z, v.w};
#pragma unroll
        for (int j = 0; j < 4; j++) {
            int c = tid * 4 + j;
            float xn = (xv[j] - mu) * rs * gamma[c] + beta[c];
            __nv_bfloat16 hi = __float2bfloat16(xn);
            g_xn_hi[base + j] = hi;
            g_xn_lo[base + j] = __float2bfloat16(xn - __bfloat162float(hi));
        }
    } else if ((int)blockIdx.x < seq + WSPLIT_BLOCKS) {
        __shared__ float tile[32][33];
        int wb = blockIdx.x - seq;
        int k0 = (wb / (NPAD / 32)) * 32, n0 = (wb % (NPAD / 32)) * 32;
        int tx = threadIdx.x & 31, ty = threadIdx.x >> 5;
#pragma unroll
        for (int i = 0; i < 4; i++) {
            int k = k0 + ty + i * 8, n = n0 + tx;
            tile[ty + i * 8][tx] = (n < NOUT) ? W[k * NOUT + n] : 0.0f;
        }
        __syncthreads();
#pragma unroll
        for (int i = 0; i < 4; i++) {
            int n = n0 + ty + i * 8, k = k0 + tx;
            float w = tile[tx][ty + i * 8];
            __nv_bfloat16 hi = __float2bfloat16(w);
            size_t idx = (size_t)n * DM + k;
            g_wT_hi[idx] = hi;
            g_wT_lo[idx] = __float2bfloat16(w - __bfloat162float(hi));
        }
    } else {
        // zero the kinematics section: NIMU*seq floats, 1024 floats per block
        int zb = blockIdx.x - seq - WSPLIT_BLOCKS;
        size_t i = (size_t)zb * 256 + threadIdx.x;
        size_t n4 = (size_t)(NIMU * seq) / 4;
        if (i < n4) ((float4*)out)[i] = make_float4(0.f, 0.f, 0.f, 0.f);
    }
}

// ---- mma.sync 3-split bf16 GEMM (R7 config) with s-offset ----
#define LOAD_STAGE(kc, s) do {                                          \
    uint32_t base_ = sb + (uint32_t)(s) * STAGEB;                       \
    _Pragma("unroll")                                                   \
    for (int i_ = 0; i_ < 2; i_++) {                                    \
        int seg_ = tid + i_ * 512;                                      \
        int rr_ = seg_ >> 3, cc_ = seg_ & 7;                            \
        uint32_t sw_ = SWZ128(rr_ * 128 + cc_ * 16);                    \
        size_t ga_ = (size_t)(bm + rr_) * DM + (kc) * KC + cc_ * 8;     \
        size_t gb_ = (size_t)(bn + rr_) * DM + (kc) * KC + cc_ * 8;     \
        cp16(base_ + sw_,             g_xn_hi + ga_);                   \
        cp16(base_ + 16384 + sw_,     g_xn_lo + ga_);                   \
        cp16(base_ + 32768 + sw_,     g_wT_hi + gb_);                   \
        cp16(base_ + 49152 + sw_,     g_wT_lo + gb_);                   \
    }                                                                   \
    CP_COMMIT();                                                        \
} while (0)

__global__ __launch_bounds__(512) void gemm_kernel(int s_off) {
    extern __shared__ __align__(1024) char smem[];
    uint32_t sb = smem_u32(smem);
    int tid = threadIdx.x, wid = tid >> 5, lane = tid & 31;
    int bm = blockIdx.x * 128 + s_off, bn = blockIdx.y * 128;
    int wm = wid & 3, wn = wid >> 2;

    LOAD_STAGE(0, 0);

    float acc[2][4][4];
#pragma unroll
    for (int i = 0; i < 2; i++)
#pragma unroll
        for (int j = 0; j < 4; j++)
#pragma unroll
            for (int q = 0; q < 4; q++) acc[i][j][q] = 0.0f;

    int a_m = (lane & 7) + ((lane >> 3) & 1) * 8;
    int a_k = (lane >> 4) * 8;
    int b_n = (lane & 7) + ((lane >> 4) & 1) * 8;
    int b_k = ((lane >> 3) & 1) * 8;

    for (int kc = 0; kc < NCH; kc++) {
        if (kc + 1 < NCH) { LOAD_STAGE(kc + 1, (kc + 1) & 1); CP_WAIT(1); }
        else              { CP_WAIT(0); }
        __syncthreads();
        uint32_t st = sb + (uint32_t)(kc & 1) * STAGEB;
#pragma unroll
        for (int ks = 0; ks < 4; ks++) {
            uint32_t ah[2][4], al[2][4], bh[4][2], bl[4][2];
#pragma unroll
            for (int i = 0; i < 2; i++) {
                uint32_t ad = st + SWZ128((wm * 32 + i * 16 + a_m) * 128 + (ks * 16 + a_k) * 2);
                LDSM4(ah[i][0], ah[i][1], ah[i][2], ah[i][3], ad);
                LDSM4(al[i][0], al[i][1], al[i][2], al[i][3], ad + 16384);
            }
#pragma unroll
            for (int jj = 0; jj < 2; jj++) {
                uint32_t bd = st + 32768 + SWZ128((wn * 32 + jj * 16 + b_n) * 128 + (ks * 16 + b_k) * 2);
                LDSM4(bh[2*jj][0], bh[2*jj][1], bh[2*jj+1][0], bh[2*jj+1][1], bd);
                LDSM4(bl[2*jj][0], bl[2*jj][1], bl[2*jj+1][0], bl[2*jj+1][1], bd + 16384);
            }
#pragma unroll
            for (int i = 0; i < 2; i++)
#pragma unroll
                for (int j = 0; j < 4; j++) {
                    MMA(acc[i][j], ah[i], bh[j]);
                    MMA(acc[i][j], ah[i], bl[j]);
                    MMA(acc[i][j], al[i], bh[j]);
                }
        }
        __syncthreads();
    }

    int m0 = bm + wm * 32 + (lane >> 2);
    int n0 = bn + wn * 32 + 2 * (lane & 3);
#pragma unroll
    for (int i = 0; i < 2; i++)
#pragma unroll
        for (int j = 0; j < 4; j++) {
            *(float2*)(g_p + (size_t)(m0 + i * 16) * NPAD + n0 + j * 8) =
                make_float2(acc[i][j][0], acc[i][j][1]);
            *(float2*)(g_p + (size_t)(m0 + i * 16 + 8) * NPAD + n0 + j * 8) =
                make_float2(acc[i][j][2], acc[i][j][3]);
        }
}

// ---- param transform (no zeroing; s-offset) ----
__device__ __forceinline__ float softplusf(float x) {
    return (x > 20.0f) ? x : log1pf(expf(x));
}

__global__ __launch_bounds__(256) void transform_kernel(const float* __restrict__ bias,
                                                        float* __restrict__ out, int seq, int s_off) {
    __shared__ float stg[4][NIMU][33];
    int s0 = blockIdx.x * 32 + s_off;

    for (int j = threadIdx.x; j < 32 * NIMU; j += 256) {
        int sl = j / NIMU, imu = j - sl * NIMU;
        int s = s0 + sl;
        float p[12];
#pragma unroll
        for (int n = 0; n < 12; n++)
            p[n] = g_p[(size_t)s * NPAD + n * NIMU + imu] + bias[n * NIMU + imu];

        float d1 = softplusf(p[1]);
        float w1 = sqrtf(softplusf(p[0]));
        float d2 = softplusf(p[3]);
        float w2 = sqrtf(softplusf(p[2]));
        float E1 = expf(-0.5f * d1), E2 = expf(-0.5f * d2);
        float sw1, cw1, sw2, cw2, sp1, cp1, sp2, cp2;
        sincosf(w1, &sw1, &cw1);
        sincosf(w2, &sw2, &cw2);
        sincosf(p[6], &sp1, &cp1);
        sincosf(p[7], &sp2, &cp2);

        size_t t = (size_t)s * NIMU + imu;
        float4* dst = (float4*)(g_osc + t * 8);
        dst[0] = make_float4(E1 * cw1, E1 * sw1, p[4] * sp1, p[4] * cp1);
        dst[1] = make_float4(E2 * cw2, E2 * sw2, p[5] * sp2, p[5] * cp2);

        stg[0][imu][sl] = p[8];
        stg[1][imu][sl] = softplusf(p[9]);
        stg[2][imu][sl] = p[10];
        stg[3][imu][sl] = softplusf(p[11]);
    }
    __syncthreads();

    size_t sec = (size_t)NIMU * seq;
    for (int j = threadIdx.x; j < 4 * NIMU * 32; j += 256) {
        int q = j / (NIMU * 32), rem = j - q * NIMU * 32;
        int imu = rem >> 5, sl = rem & 31;
        out[(q + 1) * sec + (size_t)imu * seq + s0 + sl] = stg[q][imu][sl];
    }
}

// ---- oscillator: packed state, scalar acc, rotating retire (s-offset) ----
#define OSC_STEP_CORE                                          \
    {                                                          \
        float slo, shi;                                        \
        unpackf2(slo, shi, S);                                 \
        acc += slo;                                            \
        acc += shi;                                            \
        unsigned long long t1, t2, Sn;                         \
        MULX2(t1, Bc, C);                                      \
        MULX2(t2, A, C);                                       \
        FMAX2(Sn, A, S, t1);                                   \
        FMAX2(C, NB, S, t2);                                   \
        S = Sn;                                                \
    }

__global__ __launch_bounds__(256) void osc_kernel(float* __restrict__ out, int seq, int tsteps, int s_off) {
    int chunks = gridDim.x / NIMU;
    int imu = blockIdx.x / chunks;
    int ch  = blockIdx.x - imu * chunks;
    int lane = threadIdx.x & 31;
    int B = s_off + ch * 256 + (threadIdx.x >> 5) * 32;
    int s = B + lane;

    const float4* oc = (const float4*)(g_osc + ((size_t)s * NIMU + imu) * 8);
    float4 u = oc[0], v = oc[1];
    unsigned long long A  = packf2(u.x, v.x);
    unsigned long long Bc = packf2(u.y, v.y);
    unsigned long long NB = packf2(-u.y, -v.y);
    unsigned long long S  = packf2(u.z, v.z);
    unsigned long long C  = packf2(u.w, v.w);
    float acc = 0.0f;
    float* kout = out + (size_t)imu * seq;
    bool lane0 = (lane == 0);
    float* rbase = kout + B;

    if (B + tsteps <= seq) {
#pragma unroll 4
        for (int t = 0; t < tsteps; t++) {
            OSC_STEP_CORE
            if (lane0) { atomicAdd(rbase + t, acc); acc = 0.0f; }
            acc = __shfl_sync(0xffffffffu, acc, (lane + 1) & 31);
        }
    } else {
#pragma unroll 4
        for (int t = 0; t < tsteps; t++) {
            OSC_STEP_CORE
            if (lane0) {
                if (B + t < seq) atomicAdd(rbase + t, acc);
                acc = 0.0f;
            }
            acc = __shfl_sync(0xffffffffu, acc, (lane + 1) & 31);
        }
    }
    int pos = B + tsteps + lane;
    if (pos < seq && acc != 0.0f) atomicAdd(kout + pos, acc);
}

extern "C" void kernel_launch(void* const* d_in, const int* in_sizes, int n_in,
                              void* d_out, int out_size) {
    const float* x     = (const float*)d_in[0];
    const float* gamma = (const float*)d_in[1];
    const float* beta  = (const float*)d_in[2];
    const float* W     = (const float*)d_in[3];
    const float* b     = (const float*)d_in[4];
    float* out = (float*)d_out;

    int seq = in_sizes[0] / DM;
    int tsteps = seq < 300 ? seq : 300;
    int gemm_smem = 2 * STAGEB;   // 128 KB

    static bool init = false;
    static cudaStream_t s1;
    static cudaEvent_t evG0, evD0;
    if (!init) {
        cudaFuncSetAttribute(gemm_kernel, cudaFuncAttributeMaxDynamicSharedMemorySize, gemm_smem);
        cudaStreamCreateWithFlags(&s1, cudaStreamNonBlocking);
        cudaEventCreateWithFlags(&evG0, cudaEventDisableTiming);
        cudaEventCreateWithFlags(&evD0, cudaEventDisableTiming);
        init = true;
    }

    int c0 = (seq / 2) & ~255;          // chunk 0 size (multiple of 256 & 128)
    int c1 = seq - c0;
    int zero_blocks = (NIMU * seq / 4 + 255) / 256;

    prep_kernel<<<seq + WSPLIT_BLOCKS + zero_blocks, 256>>>(x, gamma, beta, W, out, seq);

    if (c0 >= 256 && c1 >= 256) {
        dim3 g0(c0 / 128, NPAD / 128), g1(c1 / 128, NPAD / 128);
        gemm_kernel<<<g0, 512, gemm_smem>>>(0);
        cudaEventRecord(evG0, 0);
        // side stream: chunk 0 tail
        cudaStreamWaitEvent(s1, evG0, 0);
        transform_kernel<<<c0 / 32, 256, 0, s1>>>(b, out, seq, 0);
        osc_kernel<<<NIMU * (c0 / 256), 256, 0, s1>>>(out, seq, tsteps, 0);
        cudaEventRecord(evD0, s1);
        // main stream: chunk 1
        gemm_kernel<<<g1, 512, gemm_smem>>>(c0);
        transform_kernel<<<c1 / 32, 256>>>(b, out, seq, c0);
        osc_kernel<<<NIMU * (c1 / 256), 256>>>(out, seq, tsteps, c0);
        cudaStreamWaitEvent(0, evD0, 0);
    } else {
        dim3 gg(seq / 128, NPAD / 128);
        gemm_kernel<<<gg, 512, gemm_smem>>>(0);
        transform_kernel<<<seq / 32, 256>>>(b, out, seq, 0);
        osc_kernel<<<NIMU * (seq / 256), 256>>>(out, seq, tsteps, 0);
    }
}

// round 15
// speedup vs baseline: 1.1474x; 1.1474x over previous
#include <cuda_runtime.h>
#include <cuda_bf16.h>
#include <math.h>
#include <stdint.h>

#define DM    1024
#define NIMU  72
#define NOUT  864
#define NPAD  896
#define KC    64
#define NCH   (DM / KC)
#define TILEB 16384
#define STAGEB (4 * TILEB)

__device__ __nv_bfloat16 g_xn_hi[4096 * DM];
__device__ __nv_bfloat16 g_xn_lo[4096 * DM];
__device__ __nv_bfloat16 g_wT_hi[NPAD * DM];
__device__ __nv_bfloat16 g_wT_lo[NPAD * DM];
__device__ float         g_p[4096 * NPAD];
__device__ float         g_osc[4096 * NIMU * 8];

__device__ __forceinline__ uint32_t smem_u32(const void* p) {
    uint32_t a;
    asm("{ .reg .u64 t; cvta.to.shared.u64 t, %1; cvt.u32.u64 %0, t; }" : "=r"(a) : "l"(p));
    return a;
}
#define SWZ128(o) ((o) ^ (((o) >> 3) & 0x70))

__device__ __forceinline__ void cp16(uint32_t s, const void* g) {
    asm volatile("cp.async.cg.shared.global [%0], [%1], 16;"
                 :: "r"(s), "l"(__cvta_generic_to_global(g)) : "memory");
}
#define CP_COMMIT() asm volatile("cp.async.commit_group;" ::: "memory")
#define CP_WAIT(n)  asm volatile("cp.async.wait_group %0;" :: "n"(n) : "memory")

#define LDSM4(r0, r1, r2, r3, a) \
    asm volatile("ldmatrix.sync.aligned.m8n8.x4.shared.b16 {%0,%1,%2,%3}, [%4];" \
                 : "=r"(r0), "=r"(r1), "=r"(r2), "=r"(r3) : "r"(a))

#define MMA(d, a, b) \
    asm volatile("mma.sync.aligned.m16n8k16.row.col.f32.bf16.bf16.f32 " \
                 "{%0,%1,%2,%3}, {%4,%5,%6,%7}, {%8,%9}, {%0,%1,%2,%3};" \
                 : "+f"((d)[0]), "+f"((d)[1]), "+f"((d)[2]), "+f"((d)[3]) \
                 : "r"((a)[0]), "r"((a)[1]), "r"((a)[2]), "r"((a)[3]), \
                   "r"((b)[0]), "r"((b)[1]))

#define MULX2(d, a, b) asm("mul.rn.f32x2 %0, %1, %2;" : "=l"(d) : "l"(a), "l"(b))
#define FMAX2(d, a, b, c) asm("fma.rn.f32x2 %0, %1, %2, %3;" : "=l"(d) : "l"(a), "l"(b), "l"(c))
__device__ __forceinline__ unsigned long long packf2(float lo, float hi) {
    unsigned long long r;
    asm("mov.b64 %0, {%1, %2};" : "=l"(r) : "f"(lo), "f"(hi));
    return r;
}
__device__ __forceinline__ void unpackf2(float& lo, float& hi, unsigned long long v) {
    asm("mov.b64 {%0, %1}, %2;" : "=f"(lo), "=f"(hi) : "l"(v));
}

// ---- fused prep: LN-split [0,seq) | W-split [seq, seq+896) ----
__global__ __launch_bounds__(256) void prep_kernel(const float* __restrict__ x,
                                                   const float* __restrict__ gamma,
                                                   const float* __restrict__ beta,
                                                   const float* __restrict__ W, int seq) {
    if ((int)blockIdx.x < seq) {
        int s = blockIdx.x, tid = threadIdx.x;
        const float4* xr = (const float4*)(x + (size_t)s * DM);
        float4 v = xr[tid];
        float sum = v.x + v.y + v.z + v.w;
        float sq  = v.x*v.x + v.y*v.y + v.z*v.z + v.w*v.w;
#pragma unroll
        for (int o = 16; o > 0; o >>= 1) {
            sum += __shfl_xor_sync(0xffffffffu, sum, o);
            sq  += __shfl_xor_sync(0xffffffffu, sq,  o);
        }
        __shared__ float ssum[8], ssq[8], s_mu, s_rs;
        int wid = tid >> 5, lane = tid & 31;
        if (lane == 0) { ssum[wid] = sum; ssq[wid] = sq; }
        __syncthreads();
        if (tid == 0) {
            float ts = 0.f, tq = 0.f;
#pragma unroll
            for (int i = 0; i < 8; i++) { ts += ssum[i]; tq += ssq[i]; }
            float mu  = ts * (1.0f / DM);
            float var = tq * (1.0f / DM) - mu * mu;
            s_mu = mu; s_rs = rsqrtf(var + 1e-5f);
        }
        __syncthreads();
        float mu = s_mu, rs = s_rs;
        size_t base = (size_t)s * DM + (size_t)tid * 4;
        float xv[4] = {v.x, v.y, v.z, v.w};
#pragma unroll
        for (int j = 0; j < 4; j++) {
            int c = tid * 4 + j;
            float xn = (xv[j] - mu) * rs * gamma[c] + beta[c];
            __nv_bfloat16 hi = __float2bfloat16(xn);
            g_xn_hi[base + j] = hi;
            g_xn_lo[base + j] = __float2bfloat16(xn - __bfloat162float(hi));
        }
    } else {
        __shared__ float tile[32][33];
        int wb = blockIdx.x - seq;
        int k0 = (wb / (NPAD / 32)) * 32, n0 = (wb % (NPAD / 32)) * 32;
        int tx = threadIdx.x & 31, ty = threadIdx.x >> 5;
#pragma unroll
        for (int i = 0; i < 4; i++) {
            int k = k0 + ty + i * 8, n = n0 + tx;
            tile[ty + i * 8][tx] = (n < NOUT) ? W[k * NOUT + n] : 0.0f;
        }
        __syncthreads();
#pragma unroll
        for (int i = 0; i < 4; i++) {
            int n = n0 + ty + i * 8, k = k0 + tx;
            float w = tile[tx][ty + i * 8];
            __nv_bfloat16 hi = __float2bfloat16(w);
            size_t idx = (size_t)n * DM + k;
            g_wT_hi[idx] = hi;
            g_wT_lo[idx] = __float2bfloat16(w - __bfloat162float(hi));
        }
    }
}

// ---- mma.sync 3-split bf16 GEMM (R7 config) ----
#define LOAD_STAGE(kc, s) do {                                          \
    uint32_t base_ = sb + (uint32_t)(s) * STAGEB;                       \
    _Pragma("unroll")                                                   \
    for (int i_ = 0; i_ < 2; i_++) {                                    \
        int seg_ = tid + i_ * 512;                                      \
        int rr_ = seg_ >> 3, cc_ = seg_ & 7;                            \
        uint32_t sw_ = SWZ128(rr_ * 128 + cc_ * 16);                    \
        size_t ga_ = (size_t)(bm + rr_) * DM + (kc) * KC + cc_ * 8;     \
        size_t gb_ = (size_t)(bn + rr_) * DM + (kc) * KC + cc_ * 8;     \
        cp16(base_ + sw_,             g_xn_hi + ga_);                   \
        cp16(base_ + 16384 + sw_,     g_xn_lo + ga_);                   \
        cp16(base_ + 32768 + sw_,     g_wT_hi + gb_);                   \
        cp16(base_ + 49152 + sw_,     g_wT_lo + gb_);                   \
    }                                                                   \
    CP_COMMIT();                                                        \
} while (0)

__global__ __launch_bounds__(512) void gemm_kernel() {
    extern __shared__ __align__(1024) char smem[];
    uint32_t sb = smem_u32(smem);
    int tid = threadIdx.x, wid = tid >> 5, lane = tid & 31;
    int bm = blockIdx.x * 128, bn = blockIdx.y * 128;
    int wm = wid & 3, wn = wid >> 2;

    LOAD_STAGE(0, 0);

    float acc[2][4][4];
#pragma unroll
    for (int i = 0; i < 2; i++)
#pragma unroll
        for (int j = 0; j < 4; j++)
#pragma unroll
            for (int q = 0; q < 4; q++) acc[i][j][q] = 0.0f;

    int a_m = (lane & 7) + ((lane >> 3) & 1) * 8;
    int a_k = (lane >> 4) * 8;
    int b_n = (lane & 7) + ((lane >> 4) & 1) * 8;
    int b_k = ((lane >> 3) & 1) * 8;

    for (int kc = 0; kc < NCH; kc++) {
        if (kc + 1 < NCH) { LOAD_STAGE(kc + 1, (kc + 1) & 1); CP_WAIT(1); }
        else              { CP_WAIT(0); }
        __syncthreads();
        uint32_t st = sb + (uint32_t)(kc & 1) * STAGEB;
#pragma unroll
        for (int ks = 0; ks < 4; ks++) {
            uint32_t ah[2][4], al[2][4], bh[4][2], bl[4][2];
#pragma unroll
            for (int i = 0; i < 2; i++) {
                uint32_t ad = st + SWZ128((wm * 32 + i * 16 + a_m) * 128 + (ks * 16 + a_k) * 2);
                LDSM4(ah[i][0], ah[i][1], ah[i][2], ah[i][3], ad);
                LDSM4(al[i][0], al[i][1], al[i][2], al[i][3], ad + 16384);
            }
#pragma unroll
            for (int jj = 0; jj < 2; jj++) {
                uint32_t bd = st + 32768 + SWZ128((wn * 32 + jj * 16 + b_n) * 128 + (ks * 16 + b_k) * 2);
                LDSM4(bh[2*jj][0], bh[2*jj][1], bh[2*jj+1][0], bh[2*jj+1][1], bd);
                LDSM4(bl[2*jj][0], bl[2*jj][1], bl[2*jj+1][0], bl[2*jj+1][1], bd + 16384);
            }
#pragma unroll
            for (int i = 0; i < 2; i++)
#pragma unroll
                for (int j = 0; j < 4; j++) {
                    MMA(acc[i][j], ah[i], bh[j]);
                    MMA(acc[i][j], ah[i], bl[j]);
                    MMA(acc[i][j], al[i], bh[j]);
                }
        }
        __syncthreads();
    }

    int m0 = bm + wm * 32 + (lane >> 2);
    int n0 = bn + wn * 32 + 2 * (lane & 3);
#pragma unroll
    for (int i = 0; i < 2; i++)
#pragma unroll
        for (int j = 0; j < 4; j++) {
            *(float2*)(g_p + (size_t)(m0 + i * 16) * NPAD + n0 + j * 8) =
                make_float2(acc[i][j][0], acc[i][j][1]);
            *(float2*)(g_p + (size_t)(m0 + i * 16 + 8) * NPAD + n0 + j * 8) =
                make_float2(acc[i][j][2], acc[i][j][3]);
        }
}

// ---- param transform, smem-staged coalesced output (zeroes kinematics) ----
__device__ __forceinline__ float softplusf(float x) {
    return (x > 20.0f) ? x : log1pf(expf(x));
}

__global__ __launch_bounds__(256) void transform_kernel(const float* __restrict__ bias,
                                                        float* __restrict__ out, int seq) {
    __shared__ float stg[5][NIMU][33];
    int s0 = blockIdx.x * 32;

    for (int j = threadIdx.x; j < 32 * NIMU; j += 256) {
        int sl = j / NIMU, imu = j - sl * NIMU;
        int s = s0 + sl;
        float p[12];
#pragma unroll
        for (int n = 0; n < 12; n++)
            p[n] = g_p[(size_t)s * NPAD + n * NIMU + imu] + bias[n * NIMU + imu];

        float d1 = softplusf(p[1]);
        float w1 = sqrtf(softplusf(p[0]));
        float d2 = softplusf(p[3]);
        float w2 = sqrtf(softplusf(p[2]));
        float E1 = expf(-0.5f * d1), E2 = expf(-0.5f * d2);
        float sw1, cw1, sw2, cw2, sp1, cp1, sp2, cp2;
        sincosf(w1, &sw1, &cw1);
        sincosf(w2, &sw2, &cw2);
        sincosf(p[6], &sp1, &cp1);
        sincosf(p[7], &sp2, &cp2);

        size_t t = (size_t)s * NIMU + imu;
        float4* dst = (float4*)(g_osc + t * 8);
        dst[0] = make_float4(E1 * cw1, E1 * sw1, p[4] * sp1, p[4] * cp1);
        dst[1] = make_float4(E2 * cw2, E2 * sw2, p[5] * sp2, p[5] * cp2);

        stg[0][imu][sl] = 0.0f;
        stg[1][imu][sl] = p[8];
        stg[2][imu][sl] = softplusf(p[9]);
        stg[3][imu][sl] = p[10];
        stg[4][imu][sl] = softplusf(p[11]);
    }
    __syncthreads();

    size_t sec = (size_t)NIMU * seq;
    for (int j = threadIdx.x; j < 5 * NIMU * 32; j += 256) {
        int q = j / (NIMU * 32), rem = j - q * NIMU * 32;
        int imu = rem >> 5, sl = rem & 31;
        out[q * sec + (size_t)imu * seq + s0 + sl] = stg[q][imu][sl];
    }
}

// ---- oscillator: packed state, rotating acc, smem-ring batched retire ----
#define OSC_STEP(j)                                            \
    {                                                          \
        float slo, shi;                                        \
        unpackf2(slo, shi, S);                                 \
        acc += slo;                                            \
        acc += shi;                                            \
        unsigned long long t1, t2, Sn;                         \
        MULX2(t1, Bc, C);                                      \
        MULX2(t2, A, C);                                       \
        FMAX2(Sn, A, S, t1);                                   \
        FMAX2(C, NB, S, t2);                                   \
        S = Sn;                                                \
        if (lane0) { rw[j] = acc; acc = 0.0f; }                \
        acc = __shfl_sync(0xffffffffu, acc, srcl);             \
    }

__global__ __launch_bounds__(256) void osc_kernel(float* __restrict__ out, int seq, int tsteps) {
    __shared__ float ring[8][32];
    int chunks = seq >> 8;
    int imu = blockIdx.x / chunks;
    int ch  = blockIdx.x - imu * chunks;
    int w = threadIdx.x >> 5, lane = threadIdx.x & 31;
    int B = ch * 256 + w * 32;
    int s = B + lane;

    const float4* oc = (const float4*)(g_osc + ((size_t)s * NIMU + imu) * 8);
    float4 u = oc[0], v = oc[1];
    unsigned long long A  = packf2(u.x, v.x);
    unsigned long long Bc = packf2(u.y, v.y);
    unsigned long long NB = packf2(-u.y, -v.y);
    unsigned long long S  = packf2(u.z, v.z);
    unsigned long long C  = packf2(u.w, v.w);
    float acc = 0.0f;
    float* kout = out + (size_t)imu * seq;
    bool lane0 = (lane == 0);
    int srcl = (lane + 1) & 31;
    float* rw = ring[w];
    bool bounded = (B + tsteps + 32 > seq);   // edge warp: check every retire

    int T32 = tsteps & ~31;
    for (int t0 = 0; t0 < T32; t0 += 32) {
#pragma unroll
        for (int j = 0; j < 32; j++) OSC_STEP(j)
        __syncwarp();
        float fv = rw[lane];
        int pos = B + t0 + lane;
        if (bounded) { if (pos < seq) atomicAdd(kout + pos, fv); }
        else atomicAdd(kout + pos, fv);
        __syncwarp();
    }
    int R = tsteps - T32;
    if (R) {
#pragma unroll 4
        for (int j = 0; j < R; j++) OSC_STEP(j)
        __syncwarp();
        if (lane < R) {
            float fv = rw[lane];
            int pos = B + T32 + lane;
            if (pos < seq) atomicAdd(kout + pos, fv);
        }
    }
    // drain: acc in lane l is partial for pos B + tsteps + l
    int pos = B + tsteps + lane;
    if (pos < seq && acc != 0.0f) atomicAdd(kout + pos, acc);
}

extern "C" void kernel_launch(void* const* d_in, const int* in_sizes, int n_in,
                              void* d_out, int out_size) {
    const float* x     = (const float*)d_in[0];
    const float* gamma = (const float*)d_in[1];
    const float* beta  = (const float*)d_in[2];
    const float* W     = (const float*)d_in[3];
    const float* b     = (const float*)d_in[4];
    float* out = (float*)d_out;

    int seq = in_sizes[0] / DM;
    int tsteps = seq < 300 ? seq : 300;
    int gemm_smem = 2 * STAGEB;   // 128 KB

    cudaFuncSetAttribute(gemm_kernel, cudaFuncAttributeMaxDynamicSharedMemorySize, gemm_smem);

    prep_kernel<<<seq + (DM / 32) * (NPAD / 32), 256>>>(x, gamma, beta, W, seq);
    dim3 gg(seq / 128, NPAD / 128);
    gemm_kernel<<<gg, 512, gemm_smem>>>();
    transform_kernel<<<seq / 32, 256>>>(b, out, seq);
    osc_kernel<<<NIMU * (seq / 256), 256>>>(out, seq, tsteps);
}